// round 2
// baseline (speedup 1.0000x reference)
#include <cuda_runtime.h>

// BatteryRNNCell: B=4M elementwise battery state update + output voltage.
// R2: 4 elements per thread; 59 uniform MLP-weight loads hoisted out of the
// element loop into registers (was 59 LDG per element -> LSU/issue bound).

#define DEVI __device__ __forceinline__

#define R_CONST    8.3144621f
#define F_CONST    96487.0f
#define KN_C       20000.0f
#define KP_C       20000.0f
#define VOL_C      2.2e-05f
#define VOLS_C     (0.1f * VOL_C)
#define VOLB_C     (VOL_C - VOLS_C)
#define U0P_C      4.03f
#define U0N_C      0.01f

#define ELEMS_PER_THREAD 4
#define THREADS 256

DEVI float fast_tanh(float x) {
    // tanh(x) = 1 - 2/(e^{2x}+1). Robust at both saturations, abs err ~1e-7.
    float e = __expf(2.0f * x);
    return 1.0f - __fdividef(2.0f, e + 1.0f);
}

DEVI float fast_asinh_pos(float u) {
    // u > 0 in this workload. asinh(u) = log(u + sqrt(u^2 + 1)).
    return __logf(u + sqrtf(fmaf(u, u, 1.0f)));
}

DEVI float clampf(float v, float lo, float hi) {
    return fminf(fmaxf(v, lo), hi);
}

__global__ void __launch_bounds__(THREADS) battery_cell_kernel(
    const float* __restrict__ inputs,
    const float* __restrict__ states,
    const float* __restrict__ qMax,
    const float* __restrict__ Ro,
    const float* __restrict__ Wp0, const float* __restrict__ bp0,
    const float* __restrict__ Wp2, const float* __restrict__ bp2,
    const float* __restrict__ Wp4, const float* __restrict__ bp4,
    const float* __restrict__ Wn,  const float* __restrict__ bn,
    float* __restrict__ outV, float* __restrict__ outX, int n)
{
    // ---- hoist all uniform weights into registers (once per thread) ----
    float wp0[8], wb0[8], wp2[32], wb2[4], wp4[4];
    #pragma unroll
    for (int j = 0; j < 8; j++) { wp0[j] = __ldg(&Wp0[j]); wb0[j] = __ldg(&bp0[j]); }
    #pragma unroll
    for (int j = 0; j < 32; j++) wp2[j] = __ldg(&Wp2[j]);
    #pragma unroll
    for (int j = 0; j < 4; j++)  { wb2[j] = __ldg(&bp2[j]); wp4[j] = __ldg(&Wp4[j]); }
    float wb4 = __ldg(&bp4[0]);
    float w_n = __ldg(&Wn[0]);
    float b_n = __ldg(&bn[0]);

    const int base = blockIdx.x * (THREADS * ELEMS_PER_THREAD) + threadIdx.x;
    const float4* st4 = reinterpret_cast<const float4*>(states);
    float4* ox4 = reinterpret_cast<float4*>(outX);

    #pragma unroll
    for (int k = 0; k < ELEMS_PER_THREAD; k++) {
        const int b = base + k * THREADS;
        if (b >= n) break;

        // ---- per-element loads (coalesced) ----
        float4 s0 = st4[2 * b];       // Tb, Vo, Vsn, Vsp
        float4 s1 = st4[2 * b + 1];   // qnB, qnS, qpB, qpS
        float i   = inputs[b];
        float qM  = qMax[b];
        float ro  = Ro[b];

        float Tb = s0.x, Vo = s0.y, Vsn = s0.z, Vsp = s0.w;
        float qnB = s1.x, qnS = s1.y, qpB = s1.z, qpS = s1.w;

        // qSMax = qMax * 10000 * VOLS/VOL = qMax * 1000
        float inv_qSMax = __fdividef(1.0f, qM * 1000.0f);

        // ---- getNextState ----
        float xpS = clampf(qpS * inv_qSMax, 1e-18f, 1.0f);
        float xnS = clampf(qnS * inv_qSMax, 1e-18f, 1.0f);
        float Jn0 = 1e-18f + KN_C * (sqrtf(1.0f - xnS) * sqrtf(xnS));
        float Jp0 = 1e-18f + KP_C * (sqrtf(1.0f - xpS) * sqrtf(xpS));

        const float cB = 1.0f / (VOLB_C * 7.0e6f);
        const float cS = 1.0f / (VOLS_C * 7.0e6f);
        float qdn = qnB * cB - qnS * cS;
        float qdp = qpB * cB - qpS * cS;

        float J = i * 5000.0f;   // i/SN == i/SP

        float VoNom  = i * ro * 10.0f;
        const float C1 = R_CONST / F_CONST / 0.5f;
        float VsnNom = C1 * Tb * fast_asinh_pos(__fdividef(J, 2.0f * Jn0));
        float VspNom = C1 * Tb * fast_asinh_pos(__fdividef(J, 2.0f * Jp0));

        float Tb2  = Tb;
        float Vo2  = Vo  + (VoNom  - Vo ) * (1.0f / 10.0f);
        float Vsn2 = Vsn + (VsnNom - Vsn) * (1.0f / 90.0f);
        float Vsp2 = Vsp + (VspNom - Vsp) * (1.0f / 90.0f);
        float qnB2 = qnB - qdn;
        float qnS2 = qnS + qdn - i;
        float qpB2 = qpB - qdp;
        float qpS2 = qpS + i + qdp;

        // ---- getNextOutput ----
        float xpo = qpS2 * inv_qSMax;
        float xno = qnS2 * inv_qSMax;

        // MLP: 1 -> 8 (tanh) -> 4 (tanh) -> 1, weights in registers
        float h[8];
        #pragma unroll
        for (int j = 0; j < 8; j++)
            h[j] = fast_tanh(fmaf(wp0[j], xpo, wb0[j]));

        float VepMLP = wb4;
        #pragma unroll
        for (int m = 0; m < 4; m++) {
            float a = wb2[m];
            #pragma unroll
            for (int j = 0; j < 8; j++)
                a = fmaf(wp2[m * 8 + j], h[j], a);
            VepMLP = fmaf(wp4[m], fast_tanh(a), VepMLP);
        }
        float VenMLP = fmaf(xno, w_n, b_n);

        float ratio_p = clampf(__fdividef(1.0f - xpo, xpo), 1e-18f, 1e18f);
        float ratio_n = clampf(__fdividef(1.0f - xno, xno), 1e-18f, 1e18f);
        const float C2 = R_CONST / F_CONST;
        float Vep = U0P_C + C2 * Tb2 * __logf(ratio_p) + VepMLP;
        float Ven = U0N_C + C2 * Tb2 * __logf(ratio_n) + VenMLP;

        float V = Vep - Ven - Vo2 - Vsn2 - Vsp2;

        // ---- stores ----
        outV[b] = V;
        ox4[2 * b]     = make_float4(Tb2, Vo2, Vsn2, Vsp2);
        ox4[2 * b + 1] = make_float4(qnB2, qnS2, qpB2, qpS2);
    }
}

extern "C" void kernel_launch(void* const* d_in, const int* in_sizes, int n_in,
                              void* d_out, int out_size) {
    const float* inputs = (const float*)d_in[0];
    const float* states = (const float*)d_in[1];
    const float* qMax   = (const float*)d_in[2];
    const float* Ro     = (const float*)d_in[3];
    const float* Wp0    = (const float*)d_in[4];
    const float* bp0    = (const float*)d_in[5];
    const float* Wp2    = (const float*)d_in[6];
    const float* bp2    = (const float*)d_in[7];
    const float* Wp4    = (const float*)d_in[8];
    const float* bp4    = (const float*)d_in[9];
    const float* Wn     = (const float*)d_in[10];
    const float* bn     = (const float*)d_in[11];

    int n = in_sizes[0];  // B
    float* outV = (float*)d_out;
    float* outX = outV + n;  // XNew [B,8] follows V [B]

    int elems_per_block = THREADS * ELEMS_PER_THREAD;
    int blocks = (n + elems_per_block - 1) / elems_per_block;
    battery_cell_kernel<<<blocks, THREADS>>>(
        inputs, states, qMax, Ro, Wp0, bp0, Wp2, bp2, Wp4, bp4, Wn, bn,
        outV, outX, n);
}

// round 4
// speedup vs baseline: 1.5724x; 1.5724x over previous
#include <cuda_runtime.h>

// BatteryRNNCell, R3: tabulate the scalar->scalar Vep-MLP (1->8->4->1 tanh net)
// in a 4096-entry lerp table built by a tiny pre-kernel each call. Main kernel
// becomes a lean streaming kernel: ~90 instrs/elem instead of ~220.

#define DEVI __device__ __forceinline__

#define R_CONST    8.3144621f
#define F_CONST    96487.0f
#define KN_C       20000.0f
#define VOL_C      2.2e-05f
#define VOLS_C     (0.1f * VOL_C)
#define VOLB_C     (VOL_C - VOLS_C)
#define U0P_C      4.03f
#define U0N_C      0.01f

#define TAB_N 4096
#define THREADS 256

// Scratch: MLP lookup table. tab[i] = (f(x_i), f(x_{i+1}) - f(x_i)), x_i = i/TAB_N.
__device__ float2 g_mlp_tab[TAB_N];

DEVI float fast_tanh(float x) {
    // tanh(x) = 1 - 2/(e^{2x}+1). Abs err ~1e-7, robust at saturation.
    float e = __expf(2.0f * x);
    return 1.0f - __fdividef(2.0f, e + 1.0f);
}

DEVI float clampf(float v, float lo, float hi) {
    return fminf(fmaxf(v, lo), hi);
}

DEVI float mlp_eval(float x,
                    const float* __restrict__ Wp0, const float* __restrict__ bp0,
                    const float* __restrict__ Wp2, const float* __restrict__ bp2,
                    const float* __restrict__ Wp4, const float* __restrict__ bp4) {
    float h[8];
    #pragma unroll
    for (int j = 0; j < 8; j++)
        h[j] = fast_tanh(fmaf(__ldg(&Wp0[j]), x, __ldg(&bp0[j])));
    float out = __ldg(&bp4[0]);
    #pragma unroll
    for (int k = 0; k < 4; k++) {
        float a = __ldg(&bp2[k]);
        #pragma unroll
        for (int j = 0; j < 8; j++)
            a = fmaf(__ldg(&Wp2[k * 8 + j]), h[j], a);
        out = fmaf(__ldg(&Wp4[k]), fast_tanh(a), out);
    }
    return out;
}

__global__ void build_mlp_table(
    const float* __restrict__ Wp0, const float* __restrict__ bp0,
    const float* __restrict__ Wp2, const float* __restrict__ bp2,
    const float* __restrict__ Wp4, const float* __restrict__ bp4) {
    int i = blockIdx.x * blockDim.x + threadIdx.x;
    if (i >= TAB_N) return;
    const float inv = 1.0f / (float)TAB_N;
    float f0 = mlp_eval((float)i * inv,       Wp0, bp0, Wp2, bp2, Wp4, bp4);
    float f1 = mlp_eval((float)(i + 1) * inv, Wp0, bp0, Wp2, bp2, Wp4, bp4);
    g_mlp_tab[i] = make_float2(f0, f1 - f0);
}

__global__ void __launch_bounds__(THREADS) battery_cell_kernel(
    const float* __restrict__ inputs,
    const float* __restrict__ states,
    const float* __restrict__ qMax,
    const float* __restrict__ Ro,
    const float* __restrict__ Wn,  const float* __restrict__ bn,
    float* __restrict__ outV, float* __restrict__ outX, int n)
{
    int b = blockIdx.x * blockDim.x + threadIdx.x;
    if (b >= n) return;

    // ---- coalesced per-element loads ----
    const float4* st4 = reinterpret_cast<const float4*>(states);
    float4 s0 = st4[2 * b];       // Tb, Vo, Vsn, Vsp
    float4 s1 = st4[2 * b + 1];   // qnB, qnS, qpB, qpS
    float i   = inputs[b];
    float qM  = qMax[b];
    float ro  = Ro[b];

    float Tb = s0.x, Vo = s0.y, Vsn = s0.z, Vsp = s0.w;
    float qnB = s1.x, qnS = s1.y, qpB = s1.z, qpS = s1.w;

    // qSMax = qMax * 10000 * (VOLS/VOL) = qMax * 1000
    float inv_qSMax = __fdividef(1.0f, qM * 1000.0f);

    // ---- getNextState ----
    float xpS = clampf(qpS * inv_qSMax, 1e-18f, 1.0f);
    float xnS = clampf(qnS * inv_qSMax, 1e-18f, 1.0f);
    // (1-x)^.5 * x^.5 == sqrt(x*(1-x)) for x in [0,1]
    float Jn0 = 1e-18f + KN_C * sqrtf(xnS - xnS * xnS);
    float Jp0 = 1e-18f + KN_C * sqrtf(xpS - xpS * xpS);

    const float cB = 1.0f / (VOLB_C * 7.0e6f);
    const float cS = 1.0f / (VOLS_C * 7.0e6f);
    float qdn = qnB * cB - qnS * cS;
    float qdp = qpB * cB - qpS * cS;

    float J = i * 5000.0f;  // i/SN == i/SP

    float VoNom  = i * ro * 10.0f;
    const float C1 = R_CONST / F_CONST / 0.5f;
    // asinh(u) = log(u + sqrt(u^2+1)), u > 0 here
    float un = __fdividef(J, 2.0f * Jn0);
    float up = __fdividef(J, 2.0f * Jp0);
    float VsnNom = C1 * Tb * __logf(un + sqrtf(fmaf(un, un, 1.0f)));
    float VspNom = C1 * Tb * __logf(up + sqrtf(fmaf(up, up, 1.0f)));

    float Tb2  = Tb;
    float Vo2  = Vo  + (VoNom  - Vo ) * (1.0f / 10.0f);
    float Vsn2 = Vsn + (VsnNom - Vsn) * (1.0f / 90.0f);
    float Vsp2 = Vsp + (VspNom - Vsp) * (1.0f / 90.0f);
    float qnB2 = qnB - qdn;
    float qnS2 = qnS + qdn - i;
    float qpB2 = qpB - qdp;
    float qpS2 = qpS + i + qdp;

    // ---- getNextOutput ----
    float xpo = qpS2 * inv_qSMax;
    float xno = qnS2 * inv_qSMax;

    // VepMLP via table lerp (clamped index; linear extrapolation outside [0,1])
    float t = xpo * (float)TAB_N;
    float fi = floorf(t);
    int idx = min(max((int)fi, 0), TAB_N - 1);
    float2 tv = __ldg(&g_mlp_tab[idx]);
    float VepMLP = fmaf(tv.y, t - (float)idx, tv.x);

    float VenMLP = fmaf(xno, __ldg(&Wn[0]), __ldg(&bn[0]));

    float ratio_p = clampf(__fdividef(1.0f - xpo, xpo), 1e-18f, 1e18f);
    float ratio_n = clampf(__fdividef(1.0f - xno, xno), 1e-18f, 1e18f);
    const float C2 = R_CONST / F_CONST;
    float Vep = U0P_C + C2 * Tb2 * __logf(ratio_p) + VepMLP;
    float Ven = U0N_C + C2 * Tb2 * __logf(ratio_n) + VenMLP;

    float V = Vep - Ven - Vo2 - Vsn2 - Vsp2;

    // ---- stores ----
    outV[b] = V;
    float4* ox4 = reinterpret_cast<float4*>(outX);
    ox4[2 * b]     = make_float4(Tb2, Vo2, Vsn2, Vsp2);
    ox4[2 * b + 1] = make_float4(qnB2, qnS2, qpB2, qpS2);
}

extern "C" void kernel_launch(void* const* d_in, const int* in_sizes, int n_in,
                              void* d_out, int out_size) {
    const float* inputs = (const float*)d_in[0];
    const float* states = (const float*)d_in[1];
    const float* qMax   = (const float*)d_in[2];
    const float* Ro     = (const float*)d_in[3];
    const float* Wp0    = (const float*)d_in[4];
    const float* bp0    = (const float*)d_in[5];
    const float* Wp2    = (const float*)d_in[6];
    const float* bp2    = (const float*)d_in[7];
    const float* Wp4    = (const float*)d_in[8];
    const float* bp4    = (const float*)d_in[9];
    const float* Wn     = (const float*)d_in[10];
    const float* bn     = (const float*)d_in[11];

    int n = in_sizes[0];  // B
    float* outV = (float*)d_out;
    float* outX = outV + n;  // XNew [B,8] follows V [B]

    build_mlp_table<<<TAB_N / THREADS, THREADS>>>(Wp0, bp0, Wp2, bp2, Wp4, bp4);

    int blocks = (n + THREADS - 1) / THREADS;
    battery_cell_kernel<<<blocks, THREADS>>>(
        inputs, states, qMax, Ro, Wn, bn, outV, outX, n);
}